// round 13
// baseline (speedup 1.0000x reference)
#include <cuda_runtime.h>
#include <cuda_fp16.h>
#include <cuda_bf16.h>
#include <cstdint>
#include <cstring>

#define NN 100000
#define NE 800000
#define DM 128

typedef unsigned long long u64;

__device__ __forceinline__ uint32_t smem_to_u32(const void* p) {
    uint32_t a;
    asm("{ .reg .u64 t; cvta.to.shared.u64 t, %1; cvt.u32.u64 %0, t; }" : "=r"(a) : "l"(p));
    return a;
}
__device__ __forceinline__ uint32_t h2_to_u32(__half2 h) {
    uint32_t u;
    memcpy(&u, &h, 4);
    return u;
}
__device__ __forceinline__ void ldsm4(uint32_t* r, uint32_t addr) {
    asm volatile("ldmatrix.sync.aligned.m8n8.x4.shared.b16 {%0,%1,%2,%3}, [%4];"
        : "=r"(r[0]), "=r"(r[1]), "=r"(r[2]), "=r"(r[3]) : "r"(addr));
}
__device__ __forceinline__ void mma16816(float* c, const uint32_t* a, const uint32_t* b) {
    asm volatile(
        "mma.sync.aligned.m16n8k16.row.col.f32.f16.f16.f32 "
        "{%0,%1,%2,%3}, {%4,%5,%6,%7}, {%8,%9}, {%0,%1,%2,%3};"
        : "+f"(c[0]), "+f"(c[1]), "+f"(c[2]), "+f"(c[3])
        : "r"(a[0]), "r"(a[1]), "r"(a[2]), "r"(a[3]), "r"(b[0]), "r"(b[1]));
}
__device__ __forceinline__ int ld_acquire(const int* p) {
    int v;
    asm volatile("ld.acquire.gpu.global.b32 %0, [%1];" : "=r"(v) : "l"(p) : "memory");
    return v;
}
__device__ __forceinline__ void st_release(int* p, int v) {
    asm volatile("st.release.gpu.global.b32 [%0], %1;" :: "l"(p), "r"(v) : "memory");
}

// ---------------- scratch (device globals: no cudaMalloc allowed) ----------------
__device__ float  g_deg[NN];
__device__ float  g_dis[NN];
__device__ int    g_cnt[NN];
__device__ int    g_off[NN + 1];
__device__ int    g_cur[NN];
__device__ uint2  g_ew[2 * NE];              // packed (src, w-bits) per directed edge
__device__ __half g_aggh[(size_t)NN * DM];   // aggregation result, fp16 (A of GEMM)
__device__ __half g_xh[(size_t)NN * DM];     // fp16 node table (gather + L1 residual)
__device__ __half g_xh2[(size_t)NN * DM];    // L1 output (L2 gather + residual)
__device__ __half g_wt1[DM * DM];            // W1^T fp16, [n][k]
__device__ __half g_wt2[DM * DM];            // W2^T fp16, [n][k]

#define SCB 256
#define SNB ((NN + SCB - 1) / SCB)   // 391 scan blocks
__device__ int g_flag[SNB];          // blockSum+1, 0 = not ready (release/acquire)

// ---------------- prep: zero counters/flags + nodes->fp16 + W^T->fp16 ------------
__global__ void k_prep(const float* __restrict__ x, const float* __restrict__ W1,
                       const float* __restrict__ W2) {
    int b = blockIdx.x;
    if (b < 64) {
        int i = b * 256 + threadIdx.x;       // 0..16383
        int n = i & 127, k = i >> 7;
        g_wt1[n * DM + k] = __float2half_rn(__ldg(&W1[i]));
        g_wt2[n * DM + k] = __float2half_rn(__ldg(&W2[i]));
    } else if (b < 64 + SNB) {
        int i = (b - 64) * 256 + threadIdx.x;
        if (i < NN) { g_deg[i] = 0.f; g_cnt[i] = 0; }
        if (i < SNB) g_flag[i] = 0;
    } else {
        int i = (b - 64 - SNB) * 256 + threadIdx.x;
        const int N4 = NN * DM / 4;
        if (i < N4) {
            float4 v = __ldg(&((const float4*)x)[i]);
            ((__half2*)g_xh)[2 * i]     = __floats2half2_rn(v.x, v.y);
            ((__half2*)g_xh)[2 * i + 1] = __floats2half2_rn(v.z, v.w);
        }
    }
}

// ---------------- build kernels ----------------
__global__ void k_deg(const int* __restrict__ s, const int* __restrict__ r,
                      const float* __restrict__ e) {
    int i = blockIdx.x * blockDim.x + threadIdx.x;
    if (i < NE) {
        int a = s[i], b = r[i];
        float ev = e[i];
        atomicAdd(&g_deg[a], ev);
        atomicAdd(&g_deg[b], ev);
        atomicAdd(&g_cnt[a], 1);
        atomicAdd(&g_cnt[b], 1);
    }
}

// single-pass scan (decoupled lookback) + dis computation, one launch
__global__ void k_scan() {
    __shared__ int sh[SCB];
    __shared__ int red[SCB];
    int b = blockIdx.x, t = threadIdx.x;
    int i = b * SCB + t;
    int v = 0;
    if (i < NN) {
        v = g_cnt[i];
        float d = g_deg[i];
        g_dis[i] = (d > 0.f) ? rsqrtf(d) : 0.f;
    }
    sh[t] = v;
    __syncthreads();
    // Kogge-Stone inclusive scan over the block
    for (int d = 1; d < SCB; d <<= 1) {
        int x = (t >= d) ? sh[t - d] : 0;
        __syncthreads();
        sh[t] += x;
        __syncthreads();
    }
    // publish blockSum+1 (release)
    if (t == SCB - 1) st_release(&g_flag[b], sh[t] + 1);
    // lookback: sum all predecessor block sums
    int s = 0;
    for (int j = t; j < b; j += SCB) {
        int f;
        do { f = ld_acquire(&g_flag[j]); } while (f == 0);
        s += f - 1;
    }
    red[t] = s;
    __syncthreads();
    for (int d = SCB / 2; d > 0; d >>= 1) {
        if (t < d) red[t] += red[t + d];
        __syncthreads();
    }
    int prefix = red[0];
    if (i < NN) {
        int excl = prefix + sh[t] - v;
        g_off[i] = excl;
        g_cur[i] = excl;
    }
    if (b == SNB - 1 && t == SCB - 1) g_off[NN] = prefix + sh[t];
}

__global__ void k_fill(const int* __restrict__ s, const int* __restrict__ r,
                       const float* __restrict__ e) {
    int i = blockIdx.x * blockDim.x + threadIdx.x;
    if (i < NE) {
        int a = s[i], b = r[i];
        float w = g_dis[a] * e[i] * g_dis[b];
        uint32_t wb = __float_as_uint(w);
        int p = atomicAdd(&g_cur[b], 1);
        g_ew[p] = make_uint2((uint32_t)a, wb);
        int q = atomicAdd(&g_cur[a], 1);
        g_ew[q] = make_uint2((uint32_t)b, wb);
    }
}

// ---------------- aggregation: one warp per node, fp16 gather, MLP=4 -------------
__device__ __forceinline__ void acc_edge(float4& acc, float w, uint2 u) {
    __half2 h0 = *(__half2*)&u.x;
    __half2 h1 = *(__half2*)&u.y;
    float2 f0 = __half22float2(h0);
    float2 f1 = __half22float2(h1);
    acc.x = fmaf(w, f0.x, acc.x);
    acc.y = fmaf(w, f0.y, acc.y);
    acc.z = fmaf(w, f1.x, acc.z);
    acc.w = fmaf(w, f1.y, acc.w);
}

__global__ void k_agg(int layer) {
    int warp = (blockIdx.x * blockDim.x + threadIdx.x) >> 5;
    int lane = threadIdx.x & 31;
    if (warp >= NN) return;
    int beg = g_off[warp], end = g_off[warp + 1];
    float4 acc = make_float4(0.f, 0.f, 0.f, 0.f);
    const uint2* __restrict__ xh2 =
        (const uint2*)((layer == 1) ? g_xh : g_xh2);

    int j = beg;
    for (; j + 4 <= end; j += 4) {
        uint2 e0 = __ldg(&g_ew[j + 0]);
        uint2 e1 = __ldg(&g_ew[j + 1]);
        uint2 e2 = __ldg(&g_ew[j + 2]);
        uint2 e3 = __ldg(&g_ew[j + 3]);
        uint2 u0 = __ldg(&xh2[(size_t)e0.x * 32 + lane]);
        uint2 u1 = __ldg(&xh2[(size_t)e1.x * 32 + lane]);
        uint2 u2 = __ldg(&xh2[(size_t)e2.x * 32 + lane]);
        uint2 u3 = __ldg(&xh2[(size_t)e3.x * 32 + lane]);
        acc_edge(acc, __uint_as_float(e0.y), u0);
        acc_edge(acc, __uint_as_float(e1.y), u1);
        acc_edge(acc, __uint_as_float(e2.y), u2);
        acc_edge(acc, __uint_as_float(e3.y), u3);
    }
    {
        int rem = end - j;
        uint2 ez = make_uint2(0u, 0u);
        uint2 e0 = (rem > 0) ? __ldg(&g_ew[j + 0]) : ez;
        uint2 e1 = (rem > 1) ? __ldg(&g_ew[j + 1]) : ez;
        uint2 e2 = (rem > 2) ? __ldg(&g_ew[j + 2]) : ez;
        uint2 z = make_uint2(0u, 0u);
        uint2 u0 = (rem > 0) ? __ldg(&xh2[(size_t)e0.x * 32 + lane]) : z;
        uint2 u1 = (rem > 1) ? __ldg(&xh2[(size_t)e1.x * 32 + lane]) : z;
        uint2 u2 = (rem > 2) ? __ldg(&xh2[(size_t)e2.x * 32 + lane]) : z;
        acc_edge(acc, (rem > 0) ? __uint_as_float(e0.y) : 0.f, u0);
        acc_edge(acc, (rem > 1) ? __uint_as_float(e1.y) : 0.f, u1);
        acc_edge(acc, (rem > 2) ? __uint_as_float(e2.y) : 0.f, u2);
    }
    uint2 hv;
    hv.x = h2_to_u32(__floats2half2_rn(acc.x, acc.y));
    hv.y = h2_to_u32(__floats2half2_rn(acc.z, acc.w));
    ((uint2*)g_aggh)[(size_t)warp * 32 + lane] = hv;
}

// ---------------- HMMA GEMM ------------------------------------------------------
// mode 1 (layer 1): g_xh2(fp16) = g_xh(fp16 residual) + A@W1 + b
// mode 2 (layer 2): out(fp32)   = g_xh2(fp16 residual) + A@W2 + b
#define SAW 136

__global__ void __launch_bounds__(256)
k_gemm_mma(const float* __restrict__ bias, float* __restrict__ out, int mode) {
    extern __shared__ __half sh[];
    __half* sA = sh;                         // [128][SAW]
    __half* sB = sh + 128 * SAW;             // [128][SAW]  (W^T: [n][k])
    float* sBias = (float*)(sh + 2 * 128 * SAW);

    int tid = threadIdx.x;
    int w = tid >> 5, l = tid & 31;
    int rowBase = blockIdx.x * 128;

    if (tid < 128) sBias[tid] = __ldg(&bias[tid]);

    // load A tile from g_aggh (128 rows x 64 half2)
    const __half2* ag = (const __half2*)g_aggh;
#pragma unroll
    for (int i = 0; i < 32; i++) {
        int idx = tid + i * 256;             // 0..8191
        int row = idx >> 6;
        int kk = idx & 63;
        int grow = rowBase + row;
        __half2 v = (grow < NN) ? __ldg(&ag[(size_t)grow * 64 + kk])
                                : __float2half2_rn(0.f);
        *(__half2*)&sA[row * SAW + kk * 2] = v;
    }
    // load B = W^T [n][k]
    {
        const __half2* wt = (const __half2*)((mode == 1) ? g_wt1 : g_wt2);
#pragma unroll
        for (int i = 0; i < 32; i++) {
            int idx = tid + i * 256;
            int n = idx >> 6;
            int kk = idx & 63;
            *(__half2*)&sB[n * SAW + kk * 2] = __ldg(&wt[idx]);
        }
    }
    __syncthreads();

    uint32_t aBase = smem_to_u32(sA);
    uint32_t bBase = smem_to_u32(sB);

    float acc[16][4];
#pragma unroll
    for (int i = 0; i < 16; i++)
#pragma unroll
        for (int jj = 0; jj < 4; jj++) acc[i][jj] = 0.f;

    int aRow = 16 * w + (l & 15);
    int aKsub = (l >> 4) * 8;
    int bNsub = ((l >> 4) & 1) * 8 + (l & 7);
    int bKsub = ((l >> 3) & 1) * 8;

#pragma unroll
    for (int s = 0; s < 8; s++) {
        uint32_t a[4];
        ldsm4(a, aBase + ((aRow * SAW + s * 16 + aKsub) << 1));
#pragma unroll
        for (int ntp = 0; ntp < 8; ntp++) {
            uint32_t b[4];
            int n = 16 * ntp + bNsub;
            ldsm4(b, bBase + ((n * SAW + s * 16 + bKsub) << 1));
            mma16816(acc[2 * ntp + 0], a, b);
            mma16816(acc[2 * ntp + 1], a, b + 2);
        }
    }

    // epilogue: fp16 residual (g_xh for L1, g_xh2 for L2) + bias
    const __half* rtab = (mode == 1) ? g_xh : g_xh2;
    int group = l >> 2, tg = l & 3;
#pragma unroll
    for (int hh = 0; hh < 2; hh++) {
        int grow = rowBase + 16 * w + group + hh * 8;
        if (grow < NN) {
            const __half* rh = &rtab[(size_t)grow * DM];
            if (mode == 1) {
                __half* hp = &g_xh2[(size_t)grow * DM];
#pragma unroll
                for (int nt = 0; nt < 16; nt++) {
                    int c = 8 * nt + 2 * tg;
                    float2 rv = __half22float2(*(const __half2*)&rh[c]);
                    float o0 = rv.x + acc[nt][hh * 2 + 0] + sBias[c];
                    float o1 = rv.y + acc[nt][hh * 2 + 1] + sBias[c + 1];
                    *(uint32_t*)&hp[c] = h2_to_u32(__floats2half2_rn(o0, o1));
                }
            } else {
                float* op = &out[(size_t)grow * DM];
#pragma unroll
                for (int nt = 0; nt < 16; nt++) {
                    int c = 8 * nt + 2 * tg;
                    float2 rv = __half22float2(*(const __half2*)&rh[c]);
                    float o0 = rv.x + acc[nt][hh * 2 + 0] + sBias[c];
                    float o1 = rv.y + acc[nt][hh * 2 + 1] + sBias[c + 1];
                    *(float2*)&op[c] = make_float2(o0, o1);
                }
            }
        }
    }
}

// ---------------- launch ----------------
extern "C" void kernel_launch(void* const* d_in, const int* in_sizes, int n_in,
                              void* d_out, int out_size) {
    const float* nodes     = (const float*)d_in[0];
    const int*   senders   = (const int*)d_in[1];
    const int*   receivers = (const int*)d_in[2];
    const float* edges     = (const float*)d_in[3];
    const float* W1 = (const float*)d_in[4];
    const float* b1 = (const float*)d_in[5];
    const float* W2 = (const float*)d_in[6];
    const float* b2 = (const float*)d_in[7];
    float* out = (float*)d_out;

    const size_t SMEM_GEMM = 2 * 128 * SAW * sizeof(__half) + DM * sizeof(float);
    cudaFuncSetAttribute(k_gemm_mma, cudaFuncAttributeMaxDynamicSharedMemorySize,
                         (int)SMEM_GEMM);

    const int T = 256;
    const int PREP_GRID = 64 + SNB + (NN * DM / 4 + T - 1) / T;

    k_prep<<<PREP_GRID, T>>>(nodes, W1, W2);
    k_deg<<<(NE + T - 1) / T, T>>>(senders, receivers, edges);
    k_scan<<<SNB, SCB>>>();            // one-pass scan + dis
    k_fill<<<(NE + T - 1) / T, T>>>(senders, receivers, edges);

    const int AGG_GRID  = (NN * 32 + T - 1) / T;       // one warp per node
    const int GEMM_GRID = (NN + 127) / 128;            // 782 tiles

    // layer 1: gather g_xh -> g_xh2 (fp16)
    k_agg<<<AGG_GRID, T>>>(1);
    k_gemm_mma<<<GEMM_GRID, T, SMEM_GEMM>>>(b1, nullptr, 1);
    // layer 2: gather g_xh2 -> out (fp32)
    k_agg<<<AGG_GRID, T>>>(2);
    k_gemm_mma<<<GEMM_GRID, T, SMEM_GEMM>>>(b2, out, 2);
}

// round 14
// speedup vs baseline: 1.0433x; 1.0433x over previous
#include <cuda_runtime.h>
#include <cuda_fp16.h>
#include <cuda_bf16.h>
#include <cstdint>
#include <cstring>

#define NN 100000
#define NE 800000
#define DM 128

typedef unsigned long long u64;

__device__ __forceinline__ uint32_t smem_to_u32(const void* p) {
    uint32_t a;
    asm("{ .reg .u64 t; cvta.to.shared.u64 t, %1; cvt.u32.u64 %0, t; }" : "=r"(a) : "l"(p));
    return a;
}
__device__ __forceinline__ uint32_t h2_to_u32(__half2 h) {
    uint32_t u;
    memcpy(&u, &h, 4);
    return u;
}
__device__ __forceinline__ void ldsm4(uint32_t* r, uint32_t addr) {
    asm volatile("ldmatrix.sync.aligned.m8n8.x4.shared.b16 {%0,%1,%2,%3}, [%4];"
        : "=r"(r[0]), "=r"(r[1]), "=r"(r[2]), "=r"(r[3]) : "r"(addr));
}
__device__ __forceinline__ void mma16816(float* c, const uint32_t* a, const uint32_t* b) {
    asm volatile(
        "mma.sync.aligned.m16n8k16.row.col.f32.f16.f16.f32 "
        "{%0,%1,%2,%3}, {%4,%5,%6,%7}, {%8,%9}, {%0,%1,%2,%3};"
        : "+f"(c[0]), "+f"(c[1]), "+f"(c[2]), "+f"(c[3])
        : "r"(a[0]), "r"(a[1]), "r"(a[2]), "r"(a[3]), "r"(b[0]), "r"(b[1]));
}
__device__ __forceinline__ int ld_acquire(const int* p) {
    int v;
    asm volatile("ld.acquire.gpu.global.b32 %0, [%1];" : "=r"(v) : "l"(p) : "memory");
    return v;
}
__device__ __forceinline__ void st_release(int* p, int v) {
    asm volatile("st.release.gpu.global.b32 [%0], %1;" :: "l"(p), "r"(v) : "memory");
}

// ---------------- scratch (device globals: no cudaMalloc allowed) ----------------
__device__ float  g_deg[NN];
__device__ float  g_dis[NN];
__device__ int    g_cnt[NN];
__device__ int    g_off[NN + 1];
__device__ uint2  g_rank[NE];                // (rank at receiver, rank at sender)
__device__ uint2  g_ew[2 * NE];              // packed (src, w-bits) per directed edge
__device__ __half g_aggh[(size_t)NN * DM];   // aggregation result, fp16 (A of GEMM)
__device__ __half g_xh[(size_t)NN * DM];     // fp16 node table (gather + L1 residual)
__device__ __half g_xh2[(size_t)NN * DM];    // L1 output (L2 gather + residual)
__device__ __half g_wt1[DM * DM];            // W1^T fp16, [n][k]
__device__ __half g_wt2[DM * DM];            // W2^T fp16, [n][k]

#define SCB 256
#define SNB ((NN + SCB - 1) / SCB)   // 391 scan blocks
__device__ int g_flag[SNB];          // blockSum+1, 0 = not ready (release/acquire)

// ---------------- prep: zero counters/flags + nodes->fp16 + W^T->fp16 ------------
__global__ void k_prep(const float* __restrict__ x, const float* __restrict__ W1,
                       const float* __restrict__ W2) {
    int b = blockIdx.x;
    if (b < 64) {
        int i = b * 256 + threadIdx.x;       // 0..16383
        int n = i & 127, k = i >> 7;
        g_wt1[n * DM + k] = __float2half_rn(__ldg(&W1[i]));
        g_wt2[n * DM + k] = __float2half_rn(__ldg(&W2[i]));
    } else if (b < 64 + SNB) {
        int i = (b - 64) * 256 + threadIdx.x;
        if (i < NN) { g_deg[i] = 0.f; g_cnt[i] = 0; }
        if (i < SNB) g_flag[i] = 0;
    } else {
        int i = (b - 64 - SNB) * 256 + threadIdx.x;
        const int N4 = NN * DM / 4;
        if (i < N4) {
            float4 v = __ldg(&((const float4*)x)[i]);
            ((__half2*)g_xh)[2 * i]     = __floats2half2_rn(v.x, v.y);
            ((__half2*)g_xh)[2 * i + 1] = __floats2half2_rn(v.z, v.w);
        }
    }
}

// ---------------- build kernels ----------------
// k_deg also captures each edge's rank within its node segment (atomic returns)
__global__ void k_deg(const int* __restrict__ s, const int* __restrict__ r,
                      const float* __restrict__ e) {
    int i = blockIdx.x * blockDim.x + threadIdx.x;
    if (i < NE) {
        int a = s[i], b = r[i];
        float ev = e[i];
        atomicAdd(&g_deg[a], ev);
        atomicAdd(&g_deg[b], ev);
        uint32_t rb = (uint32_t)atomicAdd(&g_cnt[b], 1);  // rank of a->b at b
        uint32_t ra = (uint32_t)atomicAdd(&g_cnt[a], 1);  // rank of b->a at a
        g_rank[i] = make_uint2(rb, ra);
    }
}

// single-pass scan (decoupled lookback) + dis computation, one launch
__global__ void k_scan() {
    __shared__ int sh[SCB];
    __shared__ int red[SCB];
    int b = blockIdx.x, t = threadIdx.x;
    int i = b * SCB + t;
    int v = 0;
    if (i < NN) {
        v = g_cnt[i];
        float d = g_deg[i];
        g_dis[i] = (d > 0.f) ? rsqrtf(d) : 0.f;
    }
    sh[t] = v;
    __syncthreads();
    for (int d = 1; d < SCB; d <<= 1) {
        int x = (t >= d) ? sh[t - d] : 0;
        __syncthreads();
        sh[t] += x;
        __syncthreads();
    }
    if (t == SCB - 1) st_release(&g_flag[b], sh[t] + 1);
    int s = 0;
    for (int j = t; j < b; j += SCB) {
        int f;
        do { f = ld_acquire(&g_flag[j]); } while (f == 0);
        s += f - 1;
    }
    red[t] = s;
    __syncthreads();
    for (int d = SCB / 2; d > 0; d >>= 1) {
        if (t < d) red[t] += red[t + d];
        __syncthreads();
    }
    int prefix = red[0];
    if (i < NN) g_off[i] = prefix + sh[t] - v;
    if (b == SNB - 1 && t == SCB - 1) g_off[NN] = prefix + sh[t];
}

// atomic-free fill: slot = off[node] + captured rank
__global__ void k_fill(const int* __restrict__ s, const int* __restrict__ r,
                       const float* __restrict__ e) {
    int i = blockIdx.x * blockDim.x + threadIdx.x;
    if (i < NE) {
        int a = s[i], b = r[i];
        float w = g_dis[a] * e[i] * g_dis[b];
        uint32_t wb = __float_as_uint(w);
        uint2 rk = __ldg(&g_rank[i]);
        g_ew[g_off[b] + rk.x] = make_uint2((uint32_t)a, wb);
        g_ew[g_off[a] + rk.y] = make_uint2((uint32_t)b, wb);
    }
}

// ---------------- aggregation: one warp per node, fp16 gather, MLP=4 -------------
__device__ __forceinline__ void acc_edge(float4& acc, float w, uint2 u) {
    __half2 h0 = *(__half2*)&u.x;
    __half2 h1 = *(__half2*)&u.y;
    float2 f0 = __half22float2(h0);
    float2 f1 = __half22float2(h1);
    acc.x = fmaf(w, f0.x, acc.x);
    acc.y = fmaf(w, f0.y, acc.y);
    acc.z = fmaf(w, f1.x, acc.z);
    acc.w = fmaf(w, f1.y, acc.w);
}

__global__ void k_agg(int layer) {
    int warp = (blockIdx.x * blockDim.x + threadIdx.x) >> 5;
    int lane = threadIdx.x & 31;
    if (warp >= NN) return;
    int beg = g_off[warp], end = g_off[warp + 1];
    float4 acc = make_float4(0.f, 0.f, 0.f, 0.f);
    const uint2* __restrict__ xh2 =
        (const uint2*)((layer == 1) ? g_xh : g_xh2);

    int j = beg;
    for (; j + 4 <= end; j += 4) {
        uint2 e0 = __ldg(&g_ew[j + 0]);
        uint2 e1 = __ldg(&g_ew[j + 1]);
        uint2 e2 = __ldg(&g_ew[j + 2]);
        uint2 e3 = __ldg(&g_ew[j + 3]);
        uint2 u0 = __ldg(&xh2[(size_t)e0.x * 32 + lane]);
        uint2 u1 = __ldg(&xh2[(size_t)e1.x * 32 + lane]);
        uint2 u2 = __ldg(&xh2[(size_t)e2.x * 32 + lane]);
        uint2 u3 = __ldg(&xh2[(size_t)e3.x * 32 + lane]);
        acc_edge(acc, __uint_as_float(e0.y), u0);
        acc_edge(acc, __uint_as_float(e1.y), u1);
        acc_edge(acc, __uint_as_float(e2.y), u2);
        acc_edge(acc, __uint_as_float(e3.y), u3);
    }
    {
        int rem = end - j;
        uint2 ez = make_uint2(0u, 0u);
        uint2 e0 = (rem > 0) ? __ldg(&g_ew[j + 0]) : ez;
        uint2 e1 = (rem > 1) ? __ldg(&g_ew[j + 1]) : ez;
        uint2 e2 = (rem > 2) ? __ldg(&g_ew[j + 2]) : ez;
        uint2 z = make_uint2(0u, 0u);
        uint2 u0 = (rem > 0) ? __ldg(&xh2[(size_t)e0.x * 32 + lane]) : z;
        uint2 u1 = (rem > 1) ? __ldg(&xh2[(size_t)e1.x * 32 + lane]) : z;
        uint2 u2 = (rem > 2) ? __ldg(&xh2[(size_t)e2.x * 32 + lane]) : z;
        acc_edge(acc, (rem > 0) ? __uint_as_float(e0.y) : 0.f, u0);
        acc_edge(acc, (rem > 1) ? __uint_as_float(e1.y) : 0.f, u1);
        acc_edge(acc, (rem > 2) ? __uint_as_float(e2.y) : 0.f, u2);
    }
    uint2 hv;
    hv.x = h2_to_u32(__floats2half2_rn(acc.x, acc.y));
    hv.y = h2_to_u32(__floats2half2_rn(acc.z, acc.w));
    ((uint2*)g_aggh)[(size_t)warp * 32 + lane] = hv;
}

// ---------------- HMMA GEMM ------------------------------------------------------
// mode 1 (layer 1): g_xh2(fp16) = g_xh(fp16 residual) + A@W1 + b
// mode 2 (layer 2): out(fp32)   = g_xh2(fp16 residual) + A@W2 + b
// 128x128 tile per CTA, 8 warps as 4 row-groups x 2 col-groups:
// warp w -> rows [32*(w>>1), +32), cols [64*(w&1), +64).  6 ldsm4 / warp / k-step.
#define SAW 136

__global__ void __launch_bounds__(256)
k_gemm_mma(const float* __restrict__ bias, float* __restrict__ out, int mode) {
    extern __shared__ __half sh[];
    __half* sA = sh;                         // [128][SAW]
    __half* sB = sh + 128 * SAW;             // [128][SAW]  (W^T: [n][k])
    float* sBias = (float*)(sh + 2 * 128 * SAW);

    int tid = threadIdx.x;
    int w = tid >> 5, l = tid & 31;
    int rw = w >> 1, cg = w & 1;
    int rowBase = blockIdx.x * 128;

    if (tid < 128) sBias[tid] = __ldg(&bias[tid]);

    // load A tile from g_aggh (128 rows x 64 half2)
    const __half2* ag = (const __half2*)g_aggh;
#pragma unroll
    for (int i = 0; i < 32; i++) {
        int idx = tid + i * 256;             // 0..8191
        int row = idx >> 6;
        int kk = idx & 63;
        int grow = rowBase + row;
        __half2 v = (grow < NN) ? __ldg(&ag[(size_t)grow * 64 + kk])
                                : __float2half2_rn(0.f);
        *(__half2*)&sA[row * SAW + kk * 2] = v;
    }
    // load B = W^T [n][k]
    {
        const __half2* wt = (const __half2*)((mode == 1) ? g_wt1 : g_wt2);
#pragma unroll
        for (int i = 0; i < 32; i++) {
            int idx = tid + i * 256;
            int n = idx >> 6;
            int kk = idx & 63;
            *(__half2*)&sB[n * SAW + kk * 2] = __ldg(&wt[idx]);
        }
    }
    __syncthreads();

    uint32_t aBase = smem_to_u32(sA);
    uint32_t bBase = smem_to_u32(sB);

    float acc[2][8][4];
#pragma unroll
    for (int mi = 0; mi < 2; mi++)
#pragma unroll
        for (int ni = 0; ni < 8; ni++)
#pragma unroll
            for (int jj = 0; jj < 4; jj++) acc[mi][ni][jj] = 0.f;

    int aKsub = (l >> 4) * 8;
    int bNsub = ((l >> 4) & 1) * 8 + (l & 7);
    int bKsub = ((l >> 3) & 1) * 8;
    int aRowL = (l & 15);

#pragma unroll
    for (int s = 0; s < 8; s++) {
        uint32_t a[2][4];
#pragma unroll
        for (int mi = 0; mi < 2; mi++) {
            int row = 32 * rw + 16 * mi + aRowL;
            ldsm4(a[mi], aBase + ((row * SAW + s * 16 + aKsub) << 1));
        }
        uint32_t b[4][4];
#pragma unroll
        for (int nt = 0; nt < 4; nt++) {
            int n = 64 * cg + 16 * nt + bNsub;
            ldsm4(b[nt], bBase + ((n * SAW + s * 16 + bKsub) << 1));
        }
#pragma unroll
        for (int mi = 0; mi < 2; mi++)
#pragma unroll
            for (int nt = 0; nt < 4; nt++) {
                mma16816(acc[mi][2 * nt + 0], a[mi], b[nt]);
                mma16816(acc[mi][2 * nt + 1], a[mi], b[nt] + 2);
            }
    }

    // epilogue: fp16 residual (g_xh for L1, g_xh2 for L2) + bias
    const __half* rtab = (mode == 1) ? g_xh : g_xh2;
    int group = l >> 2, tg = l & 3;
#pragma unroll
    for (int mi = 0; mi < 2; mi++) {
#pragma unroll
        for (int hh = 0; hh < 2; hh++) {
            int grow = rowBase + 32 * rw + 16 * mi + group + hh * 8;
            if (grow < NN) {
                const __half* rh = &rtab[(size_t)grow * DM];
                if (mode == 1) {
                    __half* hp = &g_xh2[(size_t)grow * DM];
#pragma unroll
                    for (int ni = 0; ni < 8; ni++) {
                        int c = 64 * cg + 8 * ni + 2 * tg;
                        float2 rv = __half22float2(*(const __half2*)&rh[c]);
                        float o0 = rv.x + acc[mi][ni][hh * 2 + 0] + sBias[c];
                        float o1 = rv.y + acc[mi][ni][hh * 2 + 1] + sBias[c + 1];
                        *(uint32_t*)&hp[c] = h2_to_u32(__floats2half2_rn(o0, o1));
                    }
                } else {
                    float* op = &out[(size_t)grow * DM];
#pragma unroll
                    for (int ni = 0; ni < 8; ni++) {
                        int c = 64 * cg + 8 * ni + 2 * tg;
                        float2 rv = __half22float2(*(const __half2*)&rh[c]);
                        float o0 = rv.x + acc[mi][ni][hh * 2 + 0] + sBias[c];
                        float o1 = rv.y + acc[mi][ni][hh * 2 + 1] + sBias[c + 1];
                        *(float2*)&op[c] = make_float2(o0, o1);
                    }
                }
            }
        }
    }
}

// ---------------- launch ----------------
extern "C" void kernel_launch(void* const* d_in, const int* in_sizes, int n_in,
                              void* d_out, int out_size) {
    const float* nodes     = (const float*)d_in[0];
    const int*   senders   = (const int*)d_in[1];
    const int*   receivers = (const int*)d_in[2];
    const float* edges     = (const float*)d_in[3];
    const float* W1 = (const float*)d_in[4];
    const float* b1 = (const float*)d_in[5];
    const float* W2 = (const float*)d_in[6];
    const float* b2 = (const float*)d_in[7];
    float* out = (float*)d_out;

    const size_t SMEM_GEMM = 2 * 128 * SAW * sizeof(__half) + DM * sizeof(float);
    cudaFuncSetAttribute(k_gemm_mma, cudaFuncAttributeMaxDynamicSharedMemorySize,
                         (int)SMEM_GEMM);

    const int T = 256;
    const int PREP_GRID = 64 + SNB + (NN * DM / 4 + T - 1) / T;

    k_prep<<<PREP_GRID, T>>>(nodes, W1, W2);
    k_deg<<<(NE + T - 1) / T, T>>>(senders, receivers, edges);
    k_scan<<<SNB, SCB>>>();            // one-pass scan + dis
    k_fill<<<(NE + T - 1) / T, T>>>(senders, receivers, edges);

    const int AGG_GRID  = (NN * 32 + T - 1) / T;       // one warp per node
    const int GEMM_GRID = (NN + 127) / 128;            // 782 tiles

    // layer 1: gather g_xh -> g_xh2 (fp16)
    k_agg<<<AGG_GRID, T>>>(1);
    k_gemm_mma<<<GEMM_GRID, T, SMEM_GEMM>>>(b1, nullptr, 1);
    // layer 2: gather g_xh2 -> out (fp32)
    k_agg<<<AGG_GRID, T>>>(2);
    k_gemm_mma<<<GEMM_GRID, T, SMEM_GEMM>>>(b2, out, 2);
}

// round 15
// speedup vs baseline: 1.0451x; 1.0018x over previous
#include <cuda_runtime.h>
#include <cuda_fp16.h>
#include <cuda_bf16.h>
#include <cstdint>
#include <cstring>

#define NN 100000
#define NE 800000
#define DM 128

typedef unsigned long long u64;

__device__ __forceinline__ uint32_t smem_to_u32(const void* p) {
    uint32_t a;
    asm("{ .reg .u64 t; cvta.to.shared.u64 t, %1; cvt.u32.u64 %0, t; }" : "=r"(a) : "l"(p));
    return a;
}
__device__ __forceinline__ uint32_t h2_to_u32(__half2 h) {
    uint32_t u;
    memcpy(&u, &h, 4);
    return u;
}
__device__ __forceinline__ void ldsm4(uint32_t* r, uint32_t addr) {
    asm volatile("ldmatrix.sync.aligned.m8n8.x4.shared.b16 {%0,%1,%2,%3}, [%4];"
        : "=r"(r[0]), "=r"(r[1]), "=r"(r[2]), "=r"(r[3]) : "r"(addr));
}
__device__ __forceinline__ void mma16816(float* c, const uint32_t* a, const uint32_t* b) {
    asm volatile(
        "mma.sync.aligned.m16n8k16.row.col.f32.f16.f16.f32 "
        "{%0,%1,%2,%3}, {%4,%5,%6,%7}, {%8,%9}, {%0,%1,%2,%3};"
        : "+f"(c[0]), "+f"(c[1]), "+f"(c[2]), "+f"(c[3])
        : "r"(a[0]), "r"(a[1]), "r"(a[2]), "r"(a[3]), "r"(b[0]), "r"(b[1]));
}
__device__ __forceinline__ int ld_acquire(const int* p) {
    int v;
    asm volatile("ld.acquire.gpu.global.b32 %0, [%1];" : "=r"(v) : "l"(p) : "memory");
    return v;
}
__device__ __forceinline__ void st_release(int* p, int v) {
    asm volatile("st.release.gpu.global.b32 [%0], %1;" :: "l"(p), "r"(v) : "memory");
}

// ---------------- scratch (device globals: no cudaMalloc allowed) ----------------
__device__ float    g_deg[NN];
__device__ float    g_dis[NN];
__device__ int      g_cnt[NN];
__device__ int      g_off[NN + 1];
__device__ uint2    g_rank[NE];                // (rank at receiver, rank at sender)
__device__ uint32_t g_ew[2 * NE];              // packed: src<<15 | fp16(w) sans sign
__device__ __half   g_aggh[(size_t)NN * DM];   // aggregation result, fp16 (A of GEMM)
__device__ __half   g_xh[(size_t)NN * DM];     // fp16 node table (gather + L1 residual)
__device__ __half   g_xh2[(size_t)NN * DM];    // L1 output (L2 gather + residual)
__device__ __half   g_wt1[DM * DM];            // W1^T fp16, [n][k]
__device__ __half   g_wt2[DM * DM];            // W2^T fp16, [n][k]

#define SCB 256
#define SNB ((NN + SCB - 1) / SCB)   // 391 scan blocks
__device__ int g_flag[SNB];          // blockSum+1, 0 = not ready (release/acquire)

// ---------------- prep: zero counters/flags + nodes->fp16 + W^T->fp16 ------------
__global__ void k_prep(const float* __restrict__ x, const float* __restrict__ W1,
                       const float* __restrict__ W2) {
    int b = blockIdx.x;
    if (b < 64) {
        int i = b * 256 + threadIdx.x;       // 0..16383
        int n = i & 127, k = i >> 7;
        g_wt1[n * DM + k] = __float2half_rn(__ldg(&W1[i]));
        g_wt2[n * DM + k] = __float2half_rn(__ldg(&W2[i]));
    } else if (b < 64 + SNB) {
        int i = (b - 64) * 256 + threadIdx.x;
        if (i < NN) { g_deg[i] = 0.f; g_cnt[i] = 0; }
        if (i < SNB) g_flag[i] = 0;
    } else {
        int i = (b - 64 - SNB) * 256 + threadIdx.x;
        const int N4 = NN * DM / 4;
        if (i < N4) {
            float4 v = __ldg(&((const float4*)x)[i]);
            ((__half2*)g_xh)[2 * i]     = __floats2half2_rn(v.x, v.y);
            ((__half2*)g_xh)[2 * i + 1] = __floats2half2_rn(v.z, v.w);
        }
    }
}

// ---------------- build kernels ----------------
// k_deg also captures each edge's rank within its node segment (atomic returns)
__global__ void k_deg(const int* __restrict__ s, const int* __restrict__ r,
                      const float* __restrict__ e) {
    int i = blockIdx.x * blockDim.x + threadIdx.x;
    if (i < NE) {
        int a = s[i], b = r[i];
        float ev = e[i];
        atomicAdd(&g_deg[a], ev);
        atomicAdd(&g_deg[b], ev);
        uint32_t rb = (uint32_t)atomicAdd(&g_cnt[b], 1);  // rank of a->b at b
        uint32_t ra = (uint32_t)atomicAdd(&g_cnt[a], 1);  // rank of b->a at a
        g_rank[i] = make_uint2(rb, ra);
    }
}

// single-pass scan (decoupled lookback) + dis computation, one launch
__global__ void k_scan() {
    __shared__ int sh[SCB];
    __shared__ int red[SCB];
    int b = blockIdx.x, t = threadIdx.x;
    int i = b * SCB + t;
    int v = 0;
    if (i < NN) {
        v = g_cnt[i];
        float d = g_deg[i];
        g_dis[i] = (d > 0.f) ? rsqrtf(d) : 0.f;
    }
    sh[t] = v;
    __syncthreads();
    for (int d = 1; d < SCB; d <<= 1) {
        int x = (t >= d) ? sh[t - d] : 0;
        __syncthreads();
        sh[t] += x;
        __syncthreads();
    }
    if (t == SCB - 1) st_release(&g_flag[b], sh[t] + 1);
    int s = 0;
    for (int j = t; j < b; j += SCB) {
        int f;
        do { f = ld_acquire(&g_flag[j]); } while (f == 0);
        s += f - 1;
    }
    red[t] = s;
    __syncthreads();
    for (int d = SCB / 2; d > 0; d >>= 1) {
        if (t < d) red[t] += red[t + d];
        __syncthreads();
    }
    int prefix = red[0];
    if (i < NN) g_off[i] = prefix + sh[t] - v;
    if (b == SNB - 1 && t == SCB - 1) g_off[NN] = prefix + sh[t];
}

// atomic-free fill: slot = off[node] + captured rank; 4B packed record
__global__ void k_fill(const int* __restrict__ s, const int* __restrict__ r,
                       const float* __restrict__ e) {
    int i = blockIdx.x * blockDim.x + threadIdx.x;
    if (i < NE) {
        int a = s[i], b = r[i];
        float w = g_dis[a] * e[i] * g_dis[b];         // w >= 0 always
        uint32_t hb = (uint32_t)__half_as_ushort(__float2half_rn(w)) & 0x7FFFu;
        uint2 rk = __ldg(&g_rank[i]);
        g_ew[g_off[b] + rk.x] = ((uint32_t)a << 15) | hb;
        g_ew[g_off[a] + rk.y] = ((uint32_t)b << 15) | hb;
    }
}

// ---------------- aggregation: one warp per node, fp16 gather, MLP=4 -------------
__device__ __forceinline__ void acc_edge(float4& acc, float w, uint2 u) {
    __half2 h0 = *(__half2*)&u.x;
    __half2 h1 = *(__half2*)&u.y;
    float2 f0 = __half22float2(h0);
    float2 f1 = __half22float2(h1);
    acc.x = fmaf(w, f0.x, acc.x);
    acc.y = fmaf(w, f0.y, acc.y);
    acc.z = fmaf(w, f1.x, acc.z);
    acc.w = fmaf(w, f1.y, acc.w);
}
__device__ __forceinline__ float unpack_w(uint32_t p) {
    return __half2float(__ushort_as_half((unsigned short)(p & 0x7FFFu)));
}

__global__ void k_agg(int layer) {
    int warp = (blockIdx.x * blockDim.x + threadIdx.x) >> 5;
    int lane = threadIdx.x & 31;
    if (warp >= NN) return;
    int beg = g_off[warp], end = g_off[warp + 1];
    float4 acc = make_float4(0.f, 0.f, 0.f, 0.f);
    const uint2* __restrict__ xh2 =
        (const uint2*)((layer == 1) ? g_xh : g_xh2);

    int j = beg;
    for (; j + 4 <= end; j += 4) {
        uint32_t p0 = __ldg(&g_ew[j + 0]);
        uint32_t p1 = __ldg(&g_ew[j + 1]);
        uint32_t p2 = __ldg(&g_ew[j + 2]);
        uint32_t p3 = __ldg(&g_ew[j + 3]);
        uint2 u0 = __ldg(&xh2[(size_t)(p0 >> 15) * 32 + lane]);
        uint2 u1 = __ldg(&xh2[(size_t)(p1 >> 15) * 32 + lane]);
        uint2 u2 = __ldg(&xh2[(size_t)(p2 >> 15) * 32 + lane]);
        uint2 u3 = __ldg(&xh2[(size_t)(p3 >> 15) * 32 + lane]);
        acc_edge(acc, unpack_w(p0), u0);
        acc_edge(acc, unpack_w(p1), u1);
        acc_edge(acc, unpack_w(p2), u2);
        acc_edge(acc, unpack_w(p3), u3);
    }
    {
        int rem = end - j;
        uint32_t p0 = (rem > 0) ? __ldg(&g_ew[j + 0]) : 0u;
        uint32_t p1 = (rem > 1) ? __ldg(&g_ew[j + 1]) : 0u;
        uint32_t p2 = (rem > 2) ? __ldg(&g_ew[j + 2]) : 0u;
        uint2 z = make_uint2(0u, 0u);
        uint2 u0 = (rem > 0) ? __ldg(&xh2[(size_t)(p0 >> 15) * 32 + lane]) : z;
        uint2 u1 = (rem > 1) ? __ldg(&xh2[(size_t)(p1 >> 15) * 32 + lane]) : z;
        uint2 u2 = (rem > 2) ? __ldg(&xh2[(size_t)(p2 >> 15) * 32 + lane]) : z;
        acc_edge(acc, (rem > 0) ? unpack_w(p0) : 0.f, u0);
        acc_edge(acc, (rem > 1) ? unpack_w(p1) : 0.f, u1);
        acc_edge(acc, (rem > 2) ? unpack_w(p2) : 0.f, u2);
    }
    uint2 hv;
    hv.x = h2_to_u32(__floats2half2_rn(acc.x, acc.y));
    hv.y = h2_to_u32(__floats2half2_rn(acc.z, acc.w));
    ((uint2*)g_aggh)[(size_t)warp * 32 + lane] = hv;
}

// ---------------- HMMA GEMM ------------------------------------------------------
// mode 1 (layer 1): g_xh2(fp16) = g_xh(fp16 residual) + A@W1 + b
// mode 2 (layer 2): out(fp32)   = g_xh2(fp16 residual) + A@W2 + b
// 128x128 tile per CTA, 8 warps as 4 row-groups x 2 col-groups:
// warp w -> rows [32*(w>>1), +32), cols [64*(w&1), +64).  6 ldsm4 / warp / k-step.
#define SAW 136

__global__ void __launch_bounds__(256)
k_gemm_mma(const float* __restrict__ bias, float* __restrict__ out, int mode) {
    extern __shared__ __half sh[];
    __half* sA = sh;                         // [128][SAW]
    __half* sB = sh + 128 * SAW;             // [128][SAW]  (W^T: [n][k])
    float* sBias = (float*)(sh + 2 * 128 * SAW);

    int tid = threadIdx.x;
    int w = tid >> 5, l = tid & 31;
    int rw = w >> 1, cg = w & 1;
    int rowBase = blockIdx.x * 128;

    if (tid < 128) sBias[tid] = __ldg(&bias[tid]);

    // load A tile from g_aggh (128 rows x 64 half2)
    const __half2* ag = (const __half2*)g_aggh;
#pragma unroll
    for (int i = 0; i < 32; i++) {
        int idx = tid + i * 256;             // 0..8191
        int row = idx >> 6;
        int kk = idx & 63;
        int grow = rowBase + row;
        __half2 v = (grow < NN) ? __ldg(&ag[(size_t)grow * 64 + kk])
                                : __float2half2_rn(0.f);
        *(__half2*)&sA[row * SAW + kk * 2] = v;
    }
    // load B = W^T [n][k]
    {
        const __half2* wt = (const __half2*)((mode == 1) ? g_wt1 : g_wt2);
#pragma unroll
        for (int i = 0; i < 32; i++) {
            int idx = tid + i * 256;
            int n = idx >> 6;
            int kk = idx & 63;
            *(__half2*)&sB[n * SAW + kk * 2] = __ldg(&wt[idx]);
        }
    }
    __syncthreads();

    uint32_t aBase = smem_to_u32(sA);
    uint32_t bBase = smem_to_u32(sB);

    float acc[2][8][4];
#pragma unroll
    for (int mi = 0; mi < 2; mi++)
#pragma unroll
        for (int ni = 0; ni < 8; ni++)
#pragma unroll
            for (int jj = 0; jj < 4; jj++) acc[mi][ni][jj] = 0.f;

    int aKsub = (l >> 4) * 8;
    int bNsub = ((l >> 4) & 1) * 8 + (l & 7);
    int bKsub = ((l >> 3) & 1) * 8;
    int aRowL = (l & 15);

#pragma unroll
    for (int s = 0; s < 8; s++) {
        uint32_t a[2][4];
#pragma unroll
        for (int mi = 0; mi < 2; mi++) {
            int row = 32 * rw + 16 * mi + aRowL;
            ldsm4(a[mi], aBase + ((row * SAW + s * 16 + aKsub) << 1));
        }
        uint32_t b[4][4];
#pragma unroll
        for (int nt = 0; nt < 4; nt++) {
            int n = 64 * cg + 16 * nt + bNsub;
            ldsm4(b[nt], bBase + ((n * SAW + s * 16 + bKsub) << 1));
        }
#pragma unroll
        for (int mi = 0; mi < 2; mi++)
#pragma unroll
            for (int nt = 0; nt < 4; nt++) {
                mma16816(acc[mi][2 * nt + 0], a[mi], b[nt]);
                mma16816(acc[mi][2 * nt + 1], a[mi], b[nt] + 2);
            }
    }

    // epilogue: fp16 residual (g_xh for L1, g_xh2 for L2) + bias
    const __half* rtab = (mode == 1) ? g_xh : g_xh2;
    int group = l >> 2, tg = l & 3;
#pragma unroll
    for (int mi = 0; mi < 2; mi++) {
#pragma unroll
        for (int hh = 0; hh < 2; hh++) {
            int grow = rowBase + 32 * rw + 16 * mi + group + hh * 8;
            if (grow < NN) {
                const __half* rh = &rtab[(size_t)grow * DM];
                if (mode == 1) {
                    __half* hp = &g_xh2[(size_t)grow * DM];
#pragma unroll
                    for (int ni = 0; ni < 8; ni++) {
                        int c = 64 * cg + 8 * ni + 2 * tg;
                        float2 rv = __half22float2(*(const __half2*)&rh[c]);
                        float o0 = rv.x + acc[mi][ni][hh * 2 + 0] + sBias[c];
                        float o1 = rv.y + acc[mi][ni][hh * 2 + 1] + sBias[c + 1];
                        *(uint32_t*)&hp[c] = h2_to_u32(__floats2half2_rn(o0, o1));
                    }
                } else {
                    float* op = &out[(size_t)grow * DM];
#pragma unroll
                    for (int ni = 0; ni < 8; ni++) {
                        int c = 64 * cg + 8 * ni + 2 * tg;
                        float2 rv = __half22float2(*(const __half2*)&rh[c]);
                        float o0 = rv.x + acc[mi][ni][hh * 2 + 0] + sBias[c];
                        float o1 = rv.y + acc[mi][ni][hh * 2 + 1] + sBias[c + 1];
                        *(float2*)&op[c] = make_float2(o0, o1);
                    }
                }
            }
        }
    }
}

// ---------------- launch ----------------
extern "C" void kernel_launch(void* const* d_in, const int* in_sizes, int n_in,
                              void* d_out, int out_size) {
    const float* nodes     = (const float*)d_in[0];
    const int*   senders   = (const int*)d_in[1];
    const int*   receivers = (const int*)d_in[2];
    const float* edges     = (const float*)d_in[3];
    const float* W1 = (const float*)d_in[4];
    const float* b1 = (const float*)d_in[5];
    const float* W2 = (const float*)d_in[6];
    const float* b2 = (const float*)d_in[7];
    float* out = (float*)d_out;

    const size_t SMEM_GEMM = 2 * 128 * SAW * sizeof(__half) + DM * sizeof(float);
    cudaFuncSetAttribute(k_gemm_mma, cudaFuncAttributeMaxDynamicSharedMemorySize,
                         (int)SMEM_GEMM);

    const int T = 256;
    const int PREP_GRID = 64 + SNB + (NN * DM / 4 + T - 1) / T;

    k_prep<<<PREP_GRID, T>>>(nodes, W1, W2);
    k_deg<<<(NE + T - 1) / T, T>>>(senders, receivers, edges);
    k_scan<<<SNB, SCB>>>();            // one-pass scan + dis
    k_fill<<<(NE + T - 1) / T, T>>>(senders, receivers, edges);

    const int AGG_GRID  = (NN * 32 + T - 1) / T;       // one warp per node
    const int GEMM_GRID = (NN + 127) / 128;            // 782 tiles

    // layer 1: gather g_xh -> g_xh2 (fp16)
    k_agg<<<AGG_GRID, T>>>(1);
    k_gemm_mma<<<GEMM_GRID, T, SMEM_GEMM>>>(b1, nullptr, 1);
    // layer 2: gather g_xh2 -> out (fp32)
    k_agg<<<AGG_GRID, T>>>(2);
    k_gemm_mma<<<GEMM_GRID, T, SMEM_GEMM>>>(b2, out, 2);
}

// round 16
// speedup vs baseline: 1.0779x; 1.0314x over previous
#include <cuda_runtime.h>
#include <cuda_fp16.h>
#include <cuda_bf16.h>
#include <cstdint>
#include <cstring>

#define NN 100000
#define NE 800000
#define DM 128

typedef unsigned long long u64;

__device__ __forceinline__ uint32_t smem_to_u32(const void* p) {
    uint32_t a;
    asm("{ .reg .u64 t; cvta.to.shared.u64 t, %1; cvt.u32.u64 %0, t; }" : "=r"(a) : "l"(p));
    return a;
}
__device__ __forceinline__ uint32_t h2_to_u32(__half2 h) {
    uint32_t u;
    memcpy(&u, &h, 4);
    return u;
}
__device__ __forceinline__ void ldsm4(uint32_t* r, uint32_t addr) {
    asm volatile("ldmatrix.sync.aligned.m8n8.x4.shared.b16 {%0,%1,%2,%3}, [%4];"
        : "=r"(r[0]), "=r"(r[1]), "=r"(r[2]), "=r"(r[3]) : "r"(addr));
}
__device__ __forceinline__ void mma16816(float* c, const uint32_t* a, const uint32_t* b) {
    asm volatile(
        "mma.sync.aligned.m16n8k16.row.col.f32.f16.f16.f32 "
        "{%0,%1,%2,%3}, {%4,%5,%6,%7}, {%8,%9}, {%0,%1,%2,%3};"
        : "+f"(c[0]), "+f"(c[1]), "+f"(c[2]), "+f"(c[3])
        : "r"(a[0]), "r"(a[1]), "r"(a[2]), "r"(a[3]), "r"(b[0]), "r"(b[1]));
}
__device__ __forceinline__ int ld_acquire(const int* p) {
    int v;
    asm volatile("ld.acquire.gpu.global.b32 %0, [%1];" : "=r"(v) : "l"(p) : "memory");
    return v;
}
__device__ __forceinline__ void st_release(int* p, int v) {
    asm volatile("st.release.gpu.global.b32 [%0], %1;" :: "l"(p), "r"(v) : "memory");
}

// ---------------- scratch (device globals: no cudaMalloc allowed) ----------------
__device__ float    g_deg[NN];
__device__ int      g_cnt[NN];
__device__ int      g_off[NN + 1];
__device__ uint2    g_offdis[NN];              // (offset, dis-bits) packed per node
__device__ uint2    g_rank[NE];                // (rank at receiver, rank at sender)
__device__ uint32_t g_ew[2 * NE];              // packed: src<<15 | fp16(w) sans sign
__device__ __half   g_aggh[(size_t)NN * DM];   // aggregation result, fp16 (A of GEMM)
__device__ __half   g_xh[(size_t)NN * DM];     // fp16 node table (gather + L1 residual)
__device__ __half   g_xh2[(size_t)NN * DM];    // L1 output (L2 gather + residual)
__device__ __half   g_wt1[DM * DM];            // W1^T fp16, [n][k]
__device__ __half   g_wt2[DM * DM];            // W2^T fp16, [n][k]

#define SCB 256
#define SNB ((NN + SCB - 1) / SCB)   // 391 scan blocks
#define DEGB ((NE + 255) / 256)      // 3125 deg blocks
__device__ int g_flag[SNB];          // blockSum+1, 0 = not ready (release/acquire)

// ---------------- zero counters/flags (must precede k_build's atomics) -----------
__global__ void k_zero() {
    int i = blockIdx.x * blockDim.x + threadIdx.x;
    if (i < NN) { g_deg[i] = 0.f; g_cnt[i] = 0; }
    if (i < SNB) g_flag[i] = 0;
}

// ---------------- build: deg/rank + W^T fp16 + nodes fp16, ONE launch ------------
// blocks [0, DEGB): degree + rank capture; [DEGB, DEGB+64): weights; rest: node cvt
__global__ void k_build(const int* __restrict__ s, const int* __restrict__ r,
                        const float* __restrict__ e, const float* __restrict__ x,
                        const float* __restrict__ W1, const float* __restrict__ W2) {
    int b = blockIdx.x;
    if (b < DEGB) {
        int i = b * 256 + threadIdx.x;
        if (i < NE) {
            int a = s[i], bb = r[i];
            float ev = e[i];
            atomicAdd(&g_deg[a], ev);
            atomicAdd(&g_deg[bb], ev);
            uint32_t rb = (uint32_t)atomicAdd(&g_cnt[bb], 1);  // rank of a->b at b
            uint32_t ra = (uint32_t)atomicAdd(&g_cnt[a], 1);   // rank of b->a at a
            g_rank[i] = make_uint2(rb, ra);
        }
    } else if (b < DEGB + 64) {
        int i = (b - DEGB) * 256 + threadIdx.x;   // 0..16383
        int n = i & 127, k = i >> 7;
        g_wt1[n * DM + k] = __float2half_rn(__ldg(&W1[i]));
        g_wt2[n * DM + k] = __float2half_rn(__ldg(&W2[i]));
    } else {
        int i = (b - DEGB - 64) * 256 + threadIdx.x;
        const int N4 = NN * DM / 4;
        if (i < N4) {
            float4 v = __ldg(&((const float4*)x)[i]);
            ((__half2*)g_xh)[2 * i]     = __floats2half2_rn(v.x, v.y);
            ((__half2*)g_xh)[2 * i + 1] = __floats2half2_rn(v.z, v.w);
        }
    }
}

// single-pass scan (decoupled lookback) + dis + packed (off,dis), one launch
__global__ void k_scan() {
    __shared__ int sh[SCB];
    __shared__ int red[SCB];
    int b = blockIdx.x, t = threadIdx.x;
    int i = b * SCB + t;
    int v = 0;
    float dis = 0.f;
    if (i < NN) {
        v = g_cnt[i];
        float d = g_deg[i];
        dis = (d > 0.f) ? rsqrtf(d) : 0.f;
    }
    sh[t] = v;
    __syncthreads();
    for (int d = 1; d < SCB; d <<= 1) {
        int x = (t >= d) ? sh[t - d] : 0;
        __syncthreads();
        sh[t] += x;
        __syncthreads();
    }
    if (t == SCB - 1) st_release(&g_flag[b], sh[t] + 1);
    int s = 0;
    for (int j = t; j < b; j += SCB) {
        int f;
        do { f = ld_acquire(&g_flag[j]); } while (f == 0);
        s += f - 1;
    }
    red[t] = s;
    __syncthreads();
    for (int d = SCB / 2; d > 0; d >>= 1) {
        if (t < d) red[t] += red[t + d];
        __syncthreads();
    }
    int prefix = red[0];
    if (i < NN) {
        int excl = prefix + sh[t] - v;
        g_off[i] = excl;
        g_offdis[i] = make_uint2((uint32_t)excl, __float_as_uint(dis));
    }
    if (b == SNB - 1 && t == SCB - 1) g_off[NN] = prefix + sh[t];
}

// atomic-free fill: slot = off[node] + captured rank; 4B packed record
// 2 scattered 8B loads per edge (packed off+dis) instead of 4 scattered 4B loads
__global__ void k_fill(const int* __restrict__ s, const int* __restrict__ r,
                       const float* __restrict__ e) {
    int i = blockIdx.x * blockDim.x + threadIdx.x;
    if (i < NE) {
        int a = s[i], b = r[i];
        uint2 oa = __ldg(&g_offdis[a]);
        uint2 ob = __ldg(&g_offdis[b]);
        float w = __uint_as_float(oa.y) * e[i] * __uint_as_float(ob.y);  // >= 0
        uint32_t hb = (uint32_t)__half_as_ushort(__float2half_rn(w)) & 0x7FFFu;
        uint2 rk = __ldg(&g_rank[i]);
        g_ew[ob.x + rk.x] = ((uint32_t)a << 15) | hb;
        g_ew[oa.x + rk.y] = ((uint32_t)b << 15) | hb;
    }
}

// ---------------- aggregation: one warp per node, fp16 gather, MLP=4 -------------
__device__ __forceinline__ void acc_edge(float4& acc, float w, uint2 u) {
    __half2 h0 = *(__half2*)&u.x;
    __half2 h1 = *(__half2*)&u.y;
    float2 f0 = __half22float2(h0);
    float2 f1 = __half22float2(h1);
    acc.x = fmaf(w, f0.x, acc.x);
    acc.y = fmaf(w, f0.y, acc.y);
    acc.z = fmaf(w, f1.x, acc.z);
    acc.w = fmaf(w, f1.y, acc.w);
}
__device__ __forceinline__ float unpack_w(uint32_t p) {
    return __half2float(__ushort_as_half((unsigned short)(p & 0x7FFFu)));
}

__global__ void k_agg(int layer) {
    int warp = (blockIdx.x * blockDim.x + threadIdx.x) >> 5;
    int lane = threadIdx.x & 31;
    if (warp >= NN) return;
    int beg = g_off[warp], end = g_off[warp + 1];
    float4 acc = make_float4(0.f, 0.f, 0.f, 0.f);
    const uint2* __restrict__ xh2 =
        (const uint2*)((layer == 1) ? g_xh : g_xh2);

    int j = beg;
    for (; j + 4 <= end; j += 4) {
        uint32_t p0 = __ldg(&g_ew[j + 0]);
        uint32_t p1 = __ldg(&g_ew[j + 1]);
        uint32_t p2 = __ldg(&g_ew[j + 2]);
        uint32_t p3 = __ldg(&g_ew[j + 3]);
        uint2 u0 = __ldg(&xh2[(size_t)(p0 >> 15) * 32 + lane]);
        uint2 u1 = __ldg(&xh2[(size_t)(p1 >> 15) * 32 + lane]);
        uint2 u2 = __ldg(&xh2[(size_t)(p2 >> 15) * 32 + lane]);
        uint2 u3 = __ldg(&xh2[(size_t)(p3 >> 15) * 32 + lane]);
        acc_edge(acc, unpack_w(p0), u0);
        acc_edge(acc, unpack_w(p1), u1);
        acc_edge(acc, unpack_w(p2), u2);
        acc_edge(acc, unpack_w(p3), u3);
    }
    {
        int rem = end - j;
        uint32_t p0 = (rem > 0) ? __ldg(&g_ew[j + 0]) : 0u;
        uint32_t p1 = (rem > 1) ? __ldg(&g_ew[j + 1]) : 0u;
        uint32_t p2 = (rem > 2) ? __ldg(&g_ew[j + 2]) : 0u;
        uint2 z = make_uint2(0u, 0u);
        uint2 u0 = (rem > 0) ? __ldg(&xh2[(size_t)(p0 >> 15) * 32 + lane]) : z;
        uint2 u1 = (rem > 1) ? __ldg(&xh2[(size_t)(p1 >> 15) * 32 + lane]) : z;
        uint2 u2 = (rem > 2) ? __ldg(&xh2[(size_t)(p2 >> 15) * 32 + lane]) : z;
        acc_edge(acc, (rem > 0) ? unpack_w(p0) : 0.f, u0);
        acc_edge(acc, (rem > 1) ? unpack_w(p1) : 0.f, u1);
        acc_edge(acc, (rem > 2) ? unpack_w(p2) : 0.f, u2);
    }
    uint2 hv;
    hv.x = h2_to_u32(__floats2half2_rn(acc.x, acc.y));
    hv.y = h2_to_u32(__floats2half2_rn(acc.z, acc.w));
    ((uint2*)g_aggh)[(size_t)warp * 32 + lane] = hv;
}

// ---------------- HMMA GEMM ------------------------------------------------------
// mode 1 (layer 1): g_xh2(fp16) = g_xh(fp16 residual) + A@W1 + b
// mode 2 (layer 2): out(fp32)   = g_xh2(fp16 residual) + A@W2 + b
// 128x128 tile per CTA, 8 warps as 4 row-groups x 2 col-groups.
#define SAW 136

__global__ void __launch_bounds__(256)
k_gemm_mma(const float* __restrict__ bias, float* __restrict__ out, int mode) {
    extern __shared__ __half sh[];
    __half* sA = sh;                         // [128][SAW]
    __half* sB = sh + 128 * SAW;             // [128][SAW]  (W^T: [n][k])
    float* sBias = (float*)(sh + 2 * 128 * SAW);

    int tid = threadIdx.x;
    int w = tid >> 5, l = tid & 31;
    int rw = w >> 1, cg = w & 1;
    int rowBase = blockIdx.x * 128;

    if (tid < 128) sBias[tid] = __ldg(&bias[tid]);

    // load A tile from g_aggh (128 rows x 64 half2)
    const __half2* ag = (const __half2*)g_aggh;
#pragma unroll
    for (int i = 0; i < 32; i++) {
        int idx = tid + i * 256;             // 0..8191
        int row = idx >> 6;
        int kk = idx & 63;
        int grow = rowBase + row;
        __half2 v = (grow < NN) ? __ldg(&ag[(size_t)grow * 64 + kk])
                                : __float2half2_rn(0.f);
        *(__half2*)&sA[row * SAW + kk * 2] = v;
    }
    // load B = W^T [n][k]
    {
        const __half2* wt = (const __half2*)((mode == 1) ? g_wt1 : g_wt2);
#pragma unroll
        for (int i = 0; i < 32; i++) {
            int idx = tid + i * 256;
            int n = idx >> 6;
            int kk = idx & 63;
            *(__half2*)&sB[n * SAW + kk * 2] = __ldg(&wt[idx]);
        }
    }
    __syncthreads();

    uint32_t aBase = smem_to_u32(sA);
    uint32_t bBase = smem_to_u32(sB);

    float acc[2][8][4];
#pragma unroll
    for (int mi = 0; mi < 2; mi++)
#pragma unroll
        for (int ni = 0; ni < 8; ni++)
#pragma unroll
            for (int jj = 0; jj < 4; jj++) acc[mi][ni][jj] = 0.f;

    int aKsub = (l >> 4) * 8;
    int bNsub = ((l >> 4) & 1) * 8 + (l & 7);
    int bKsub = ((l >> 3) & 1) * 8;
    int aRowL = (l & 15);

#pragma unroll
    for (int s = 0; s < 8; s++) {
        uint32_t a[2][4];
#pragma unroll
        for (int mi = 0; mi < 2; mi++) {
            int row = 32 * rw + 16 * mi + aRowL;
            ldsm4(a[mi], aBase + ((row * SAW + s * 16 + aKsub) << 1));
        }
        uint32_t b[4][4];
#pragma unroll
        for (int nt = 0; nt < 4; nt++) {
            int n = 64 * cg + 16 * nt + bNsub;
            ldsm4(b[nt], bBase + ((n * SAW + s * 16 + bKsub) << 1));
        }
#pragma unroll
        for (int mi = 0; mi < 2; mi++)
#pragma unroll
            for (int nt = 0; nt < 4; nt++) {
                mma16816(acc[mi][2 * nt + 0], a[mi], b[nt]);
                mma16816(acc[mi][2 * nt + 1], a[mi], b[nt] + 2);
            }
    }

    // epilogue: fp16 residual (g_xh for L1, g_xh2 for L2) + bias
    const __half* rtab = (mode == 1) ? g_xh : g_xh2;
    int group = l >> 2, tg = l & 3;
#pragma unroll
    for (int mi = 0; mi < 2; mi++) {
#pragma unroll
        for (int hh = 0; hh < 2; hh++) {
            int grow = rowBase + 32 * rw + 16 * mi + group + hh * 8;
            if (grow < NN) {
                const __half* rh = &rtab[(size_t)grow * DM];
                if (mode == 1) {
                    __half* hp = &g_xh2[(size_t)grow * DM];
#pragma unroll
                    for (int ni = 0; ni < 8; ni++) {
                        int c = 64 * cg + 8 * ni + 2 * tg;
                        float2 rv = __half22float2(*(const __half2*)&rh[c]);
                        float o0 = rv.x + acc[mi][ni][hh * 2 + 0] + sBias[c];
                        float o1 = rv.y + acc[mi][ni][hh * 2 + 1] + sBias[c + 1];
                        *(uint32_t*)&hp[c] = h2_to_u32(__floats2half2_rn(o0, o1));
                    }
                } else {
                    float* op = &out[(size_t)grow * DM];
#pragma unroll
                    for (int ni = 0; ni < 8; ni++) {
                        int c = 64 * cg + 8 * ni + 2 * tg;
                        float2 rv = __half22float2(*(const __half2*)&rh[c]);
                        float o0 = rv.x + acc[mi][ni][hh * 2 + 0] + sBias[c];
                        float o1 = rv.y + acc[mi][ni][hh * 2 + 1] + sBias[c + 1];
                        *(float2*)&op[c] = make_float2(o0, o1);
                    }
                }
            }
        }
    }
}

// ---------------- launch ----------------
extern "C" void kernel_launch(void* const* d_in, const int* in_sizes, int n_in,
                              void* d_out, int out_size) {
    const float* nodes     = (const float*)d_in[0];
    const int*   senders   = (const int*)d_in[1];
    const int*   receivers = (const int*)d_in[2];
    const float* edges     = (const float*)d_in[3];
    const float* W1 = (const float*)d_in[4];
    const float* b1 = (const float*)d_in[5];
    const float* W2 = (const float*)d_in[6];
    const float* b2 = (const float*)d_in[7];
    float* out = (float*)d_out;

    const size_t SMEM_GEMM = 2 * 128 * SAW * sizeof(__half) + DM * sizeof(float);
    cudaFuncSetAttribute(k_gemm_mma, cudaFuncAttributeMaxDynamicSharedMemorySize,
                         (int)SMEM_GEMM);

    const int T = 256;
    const int BUILD_GRID = DEGB + 64 + (NN * DM / 4 + T - 1) / T;

    k_zero<<<(NN + T - 1) / T, T>>>();
    k_build<<<BUILD_GRID, T>>>(senders, receivers, edges, nodes, W1, W2);
    k_scan<<<SNB, SCB>>>();            // one-pass scan + dis + packed (off,dis)
    k_fill<<<(NE + T - 1) / T, T>>>(senders, receivers, edges);

    const int AGG_GRID  = (NN * 32 + T - 1) / T;       // one warp per node
    const int GEMM_GRID = (NN + 127) / 128;            // 782 tiles

    // layer 1: gather g_xh -> g_xh2 (fp16)
    k_agg<<<AGG_GRID, T>>>(1);
    k_gemm_mma<<<GEMM_GRID, T, SMEM_GEMM>>>(b1, nullptr, 1);
    // layer 2: gather g_xh2 -> out (fp32)
    k_agg<<<AGG_GRID, T>>>(2);
    k_gemm_mma<<<GEMM_GRID, T, SMEM_GEMM>>>(b2, out, 2);
}

// round 17
// speedup vs baseline: 1.0999x; 1.0204x over previous
#include <cuda_runtime.h>
#include <cuda_fp16.h>
#include <cuda_bf16.h>
#include <cstdint>
#include <cstring>

#define NN 100000
#define NE 800000
#define DM 128

typedef unsigned long long u64;

__device__ __forceinline__ uint32_t smem_to_u32(const void* p) {
    uint32_t a;
    asm("{ .reg .u64 t; cvta.to.shared.u64 t, %1; cvt.u32.u64 %0, t; }" : "=r"(a) : "l"(p));
    return a;
}
__device__ __forceinline__ uint32_t h2_to_u32(__half2 h) {
    uint32_t u;
    memcpy(&u, &h, 4);
    return u;
}
__device__ __forceinline__ void ldsm4(uint32_t* r, uint32_t addr) {
    asm volatile("ldmatrix.sync.aligned.m8n8.x4.shared.b16 {%0,%1,%2,%3}, [%4];"
        : "=r"(r[0]), "=r"(r[1]), "=r"(r[2]), "=r"(r[3]) : "r"(addr));
}
__device__ __forceinline__ void mma16816(float* c, const uint32_t* a, const uint32_t* b) {
    asm volatile(
        "mma.sync.aligned.m16n8k16.row.col.f32.f16.f16.f32 "
        "{%0,%1,%2,%3}, {%4,%5,%6,%7}, {%8,%9}, {%0,%1,%2,%3};"
        : "+f"(c[0]), "+f"(c[1]), "+f"(c[2]), "+f"(c[3])
        : "r"(a[0]), "r"(a[1]), "r"(a[2]), "r"(a[3]), "r"(b[0]), "r"(b[1]));
}
__device__ __forceinline__ int ld_acquire(const int* p) {
    int v;
    asm volatile("ld.acquire.gpu.global.b32 %0, [%1];" : "=r"(v) : "l"(p) : "memory");
    return v;
}
__device__ __forceinline__ void st_release(int* p, int v) {
    asm volatile("st.release.gpu.global.b32 [%0], %1;" :: "l"(p), "r"(v) : "memory");
}

// ---------------- scratch (device globals: no cudaMalloc allowed) ----------------
__device__ u64      g_degcnt[NN];              // hi: edge count, lo: deg in 2^22 fx
__device__ int      g_off[NN + 1];
__device__ uint2    g_offdis[NN];              // (offset, dis-bits) packed per node
__device__ uint2    g_rank[NE];                // (rank at receiver, rank at sender)
__device__ uint32_t g_ew[2 * NE];              // packed: src<<15 | fp16(w) sans sign
__device__ __half   g_aggh[(size_t)NN * DM];   // aggregation result, fp16 (A of GEMM)
__device__ __half   g_xh[(size_t)NN * DM];     // fp16 node table (gather + L1 residual)
__device__ __half   g_xh2[(size_t)NN * DM];    // L1 output (L2 gather + residual)
__device__ __half   g_wt1[DM * DM];            // W1^T fp16, [n][k]
__device__ __half   g_wt2[DM * DM];            // W2^T fp16, [n][k]

#define SCB 256
#define SNB ((NN + SCB - 1) / SCB)   // 391 scan blocks
#define DEGB ((NE + 255) / 256)      // 3125 deg blocks
#define FXS 4194304.0f               // 2^22 fixed-point scale for edge weights
__device__ int g_flag[SNB];          // blockSum+1, 0 = not ready (release/acquire)

// ---------------- zero counters/flags (must precede k_build's atomics) -----------
__global__ void k_zero() {
    int i = blockIdx.x * blockDim.x + threadIdx.x;
    if (i < NN) g_degcnt[i] = 0ull;
    if (i < SNB) g_flag[i] = 0;
}

// ---------------- build: deg/rank + W^T fp16 + nodes fp16, ONE launch ------------
// blocks [0, DEGB): packed degree+count atomic (rank from return); then weights; cvt
__global__ void k_build(const int* __restrict__ s, const int* __restrict__ r,
                        const float* __restrict__ e, const float* __restrict__ x,
                        const float* __restrict__ W1, const float* __restrict__ W2) {
    int b = blockIdx.x;
    if (b < DEGB) {
        int i = b * 256 + threadIdx.x;
        if (i < NE) {
            int a = s[i], bb = r[i];
            u64 add = (1ull << 32) | (u64)(uint32_t)__float2uint_rn(e[i] * FXS);
            u64 ob = atomicAdd(&g_degcnt[bb], add);   // rank of a->b at b = hi(ob)
            u64 oa = atomicAdd(&g_degcnt[a], add);    // rank of b->a at a = hi(oa)
            g_rank[i] = make_uint2((uint32_t)(ob >> 32), (uint32_t)(oa >> 32));
        }
    } else if (b < DEGB + 64) {
        int i = (b - DEGB) * 256 + threadIdx.x;   // 0..16383
        int n = i & 127, k = i >> 7;
        g_wt1[n * DM + k] = __float2half_rn(__ldg(&W1[i]));
        g_wt2[n * DM + k] = __float2half_rn(__ldg(&W2[i]));
    } else {
        int i = (b - DEGB - 64) * 256 + threadIdx.x;
        const int N4 = NN * DM / 4;
        if (i < N4) {
            float4 v = __ldg(&((const float4*)x)[i]);
            ((__half2*)g_xh)[2 * i]     = __floats2half2_rn(v.x, v.y);
            ((__half2*)g_xh)[2 * i + 1] = __floats2half2_rn(v.z, v.w);
        }
    }
}

// single-pass scan (decoupled lookback) + dis + packed (off,dis), one launch
__global__ void k_scan() {
    __shared__ int sh[SCB];
    __shared__ int red[SCB];
    int b = blockIdx.x, t = threadIdx.x;
    int i = b * SCB + t;
    int v = 0;
    float dis = 0.f;
    if (i < NN) {
        u64 dc = g_degcnt[i];
        v = (int)(dc >> 32);
        float d = (float)(uint32_t)(dc & 0xFFFFFFFFull) * (1.0f / FXS);
        dis = (d > 0.f) ? rsqrtf(d) : 0.f;
    }
    sh[t] = v;
    __syncthreads();
    for (int d = 1; d < SCB; d <<= 1) {
        int x = (t >= d) ? sh[t - d] : 0;
        __syncthreads();
        sh[t] += x;
        __syncthreads();
    }
    if (t == SCB - 1) st_release(&g_flag[b], sh[t] + 1);
    int s = 0;
    for (int j = t; j < b; j += SCB) {
        int f;
        do { f = ld_acquire(&g_flag[j]); } while (f == 0);
        s += f - 1;
    }
    red[t] = s;
    __syncthreads();
    for (int d = SCB / 2; d > 0; d >>= 1) {
        if (t < d) red[t] += red[t + d];
        __syncthreads();
    }
    int prefix = red[0];
    if (i < NN) {
        int excl = prefix + sh[t] - v;
        g_off[i] = excl;
        g_offdis[i] = make_uint2((uint32_t)excl, __float_as_uint(dis));
    }
    if (b == SNB - 1 && t == SCB - 1) g_off[NN] = prefix + sh[t];
}

// atomic-free fill: slot = off[node] + captured rank; 4B packed record
__global__ void k_fill(const int* __restrict__ s, const int* __restrict__ r,
                       const float* __restrict__ e) {
    int i = blockIdx.x * blockDim.x + threadIdx.x;
    if (i < NE) {
        int a = s[i], b = r[i];
        uint2 oa = __ldg(&g_offdis[a]);
        uint2 ob = __ldg(&g_offdis[b]);
        float w = __uint_as_float(oa.y) * e[i] * __uint_as_float(ob.y);  // >= 0
        uint32_t hb = (uint32_t)__half_as_ushort(__float2half_rn(w)) & 0x7FFFu;
        uint2 rk = __ldg(&g_rank[i]);
        g_ew[ob.x + rk.x] = ((uint32_t)a << 15) | hb;
        g_ew[oa.x + rk.y] = ((uint32_t)b << 15) | hb;
    }
}

// ---------------- aggregation: one warp per node, fp16 gather, MLP=4 -------------
__device__ __forceinline__ void acc_edge(float4& acc, float w, uint2 u) {
    __half2 h0 = *(__half2*)&u.x;
    __half2 h1 = *(__half2*)&u.y;
    float2 f0 = __half22float2(h0);
    float2 f1 = __half22float2(h1);
    acc.x = fmaf(w, f0.x, acc.x);
    acc.y = fmaf(w, f0.y, acc.y);
    acc.z = fmaf(w, f1.x, acc.z);
    acc.w = fmaf(w, f1.y, acc.w);
}
__device__ __forceinline__ float unpack_w(uint32_t p) {
    return __half2float(__ushort_as_half((unsigned short)(p & 0x7FFFu)));
}

__global__ void k_agg(int layer) {
    int warp = (blockIdx.x * blockDim.x + threadIdx.x) >> 5;
    int lane = threadIdx.x & 31;
    if (warp >= NN) return;
    int beg = g_off[warp], end = g_off[warp + 1];
    float4 acc = make_float4(0.f, 0.f, 0.f, 0.f);
    const uint2* __restrict__ xh2 =
        (const uint2*)((layer == 1) ? g_xh : g_xh2);

    int j = beg;
    for (; j + 4 <= end; j += 4) {
        uint32_t p0 = __ldg(&g_ew[j + 0]);
        uint32_t p1 = __ldg(&g_ew[j + 1]);
        uint32_t p2 = __ldg(&g_ew[j + 2]);
        uint32_t p3 = __ldg(&g_ew[j + 3]);
        uint2 u0 = __ldg(&xh2[(size_t)(p0 >> 15) * 32 + lane]);
        uint2 u1 = __ldg(&xh2[(size_t)(p1 >> 15) * 32 + lane]);
        uint2 u2 = __ldg(&xh2[(size_t)(p2 >> 15) * 32 + lane]);
        uint2 u3 = __ldg(&xh2[(size_t)(p3 >> 15) * 32 + lane]);
        acc_edge(acc, unpack_w(p0), u0);
        acc_edge(acc, unpack_w(p1), u1);
        acc_edge(acc, unpack_w(p2), u2);
        acc_edge(acc, unpack_w(p3), u3);
    }
    {
        int rem = end - j;
        uint32_t p0 = (rem > 0) ? __ldg(&g_ew[j + 0]) : 0u;
        uint32_t p1 = (rem > 1) ? __ldg(&g_ew[j + 1]) : 0u;
        uint32_t p2 = (rem > 2) ? __ldg(&g_ew[j + 2]) : 0u;
        uint2 z = make_uint2(0u, 0u);
        uint2 u0 = (rem > 0) ? __ldg(&xh2[(size_t)(p0 >> 15) * 32 + lane]) : z;
        uint2 u1 = (rem > 1) ? __ldg(&xh2[(size_t)(p1 >> 15) * 32 + lane]) : z;
        uint2 u2 = (rem > 2) ? __ldg(&xh2[(size_t)(p2 >> 15) * 32 + lane]) : z;
        acc_edge(acc, (rem > 0) ? unpack_w(p0) : 0.f, u0);
        acc_edge(acc, (rem > 1) ? unpack_w(p1) : 0.f, u1);
        acc_edge(acc, (rem > 2) ? unpack_w(p2) : 0.f, u2);
    }
    uint2 hv;
    hv.x = h2_to_u32(__floats2half2_rn(acc.x, acc.y));
    hv.y = h2_to_u32(__floats2half2_rn(acc.z, acc.w));
    ((uint2*)g_aggh)[(size_t)warp * 32 + lane] = hv;
}

// ---------------- HMMA GEMM ------------------------------------------------------
// mode 1 (layer 1): g_xh2(fp16) = g_xh(fp16 residual) + A@W1 + b
// mode 2 (layer 2): out(fp32)   = g_xh2(fp16 residual) + A@W2 + b
// 128x128 tile per CTA, 8 warps as 4 row-groups x 2 col-groups.
#define SAW 136

__global__ void __launch_bounds__(256)
k_gemm_mma(const float* __restrict__ bias, float* __restrict__ out, int mode) {
    extern __shared__ __half sh[];
    __half* sA = sh;                         // [128][SAW]
    __half* sB = sh + 128 * SAW;             // [128][SAW]  (W^T: [n][k])
    float* sBias = (float*)(sh + 2 * 128 * SAW);

    int tid = threadIdx.x;
    int w = tid >> 5, l = tid & 31;
    int rw = w >> 1, cg = w & 1;
    int rowBase = blockIdx.x * 128;

    if (tid < 128) sBias[tid] = __ldg(&bias[tid]);

    // load A tile from g_aggh (128 rows x 64 half2)
    const __half2* ag = (const __half2*)g_aggh;
#pragma unroll
    for (int i = 0; i < 32; i++) {
        int idx = tid + i * 256;             // 0..8191
        int row = idx >> 6;
        int kk = idx & 63;
        int grow = rowBase + row;
        __half2 v = (grow < NN) ? __ldg(&ag[(size_t)grow * 64 + kk])
                                : __float2half2_rn(0.f);
        *(__half2*)&sA[row * SAW + kk * 2] = v;
    }
    // load B = W^T [n][k]
    {
        const __half2* wt = (const __half2*)((mode == 1) ? g_wt1 : g_wt2);
#pragma unroll
        for (int i = 0; i < 32; i++) {
            int idx = tid + i * 256;
            int n = idx >> 6;
            int kk = idx & 63;
            *(__half2*)&sB[n * SAW + kk * 2] = __ldg(&wt[idx]);
        }
    }
    __syncthreads();

    uint32_t aBase = smem_to_u32(sA);
    uint32_t bBase = smem_to_u32(sB);

    float acc[2][8][4];
#pragma unroll
    for (int mi = 0; mi < 2; mi++)
#pragma unroll
        for (int ni = 0; ni < 8; ni++)
#pragma unroll
            for (int jj = 0; jj < 4; jj++) acc[mi][ni][jj] = 0.f;

    int aKsub = (l >> 4) * 8;
    int bNsub = ((l >> 4) & 1) * 8 + (l & 7);
    int bKsub = ((l >> 3) & 1) * 8;
    int aRowL = (l & 15);

#pragma unroll
    for (int s = 0; s < 8; s++) {
        uint32_t a[2][4];
#pragma unroll
        for (int mi = 0; mi < 2; mi++) {
            int row = 32 * rw + 16 * mi + aRowL;
            ldsm4(a[mi], aBase + ((row * SAW + s * 16 + aKsub) << 1));
        }
        uint32_t b[4][4];
#pragma unroll
        for (int nt = 0; nt < 4; nt++) {
            int n = 64 * cg + 16 * nt + bNsub;
            ldsm4(b[nt], bBase + ((n * SAW + s * 16 + bKsub) << 1));
        }
#pragma unroll
        for (int mi = 0; mi < 2; mi++)
#pragma unroll
            for (int nt = 0; nt < 4; nt++) {
                mma16816(acc[mi][2 * nt + 0], a[mi], b[nt]);
                mma16816(acc[mi][2 * nt + 1], a[mi], b[nt] + 2);
            }
    }

    // epilogue: fp16 residual (g_xh for L1, g_xh2 for L2) + bias
    const __half* rtab = (mode == 1) ? g_xh : g_xh2;
    int group = l >> 2, tg = l & 3;
#pragma unroll
    for (int mi = 0; mi < 2; mi++) {
#pragma unroll
        for (int hh = 0; hh < 2; hh++) {
            int grow = rowBase + 32 * rw + 16 * mi + group + hh * 8;
            if (grow < NN) {
                const __half* rh = &rtab[(size_t)grow * DM];
                if (mode == 1) {
                    __half* hp = &g_xh2[(size_t)grow * DM];
#pragma unroll
                    for (int ni = 0; ni < 8; ni++) {
                        int c = 64 * cg + 8 * ni + 2 * tg;
                        float2 rv = __half22float2(*(const __half2*)&rh[c]);
                        float o0 = rv.x + acc[mi][ni][hh * 2 + 0] + sBias[c];
                        float o1 = rv.y + acc[mi][ni][hh * 2 + 1] + sBias[c + 1];
                        *(uint32_t*)&hp[c] = h2_to_u32(__floats2half2_rn(o0, o1));
                    }
                } else {
                    float* op = &out[(size_t)grow * DM];
#pragma unroll
                    for (int ni = 0; ni < 8; ni++) {
                        int c = 64 * cg + 8 * ni + 2 * tg;
                        float2 rv = __half22float2(*(const __half2*)&rh[c]);
                        float o0 = rv.x + acc[mi][ni][hh * 2 + 0] + sBias[c];
                        float o1 = rv.y + acc[mi][ni][hh * 2 + 1] + sBias[c + 1];
                        *(float2*)&op[c] = make_float2(o0, o1);
                    }
                }
            }
        }
    }
}

// ---------------- launch ----------------
extern "C" void kernel_launch(void* const* d_in, const int* in_sizes, int n_in,
                              void* d_out, int out_size) {
    const float* nodes     = (const float*)d_in[0];
    const int*   senders   = (const int*)d_in[1];
    const int*   receivers = (const int*)d_in[2];
    const float* edges     = (const float*)d_in[3];
    const float* W1 = (const float*)d_in[4];
    const float* b1 = (const float*)d_in[5];
    const float* W2 = (const float*)d_in[6];
    const float* b2 = (const float*)d_in[7];
    float* out = (float*)d_out;

    const size_t SMEM_GEMM = 2 * 128 * SAW * sizeof(__half) + DM * sizeof(float);
    cudaFuncSetAttribute(k_gemm_mma, cudaFuncAttributeMaxDynamicSharedMemorySize,
                         (int)SMEM_GEMM);

    const int T = 256;
    const int BUILD_GRID = DEGB + 64 + (NN * DM / 4 + T - 1) / T;

    k_zero<<<(NN + T - 1) / T, T>>>();
    k_build<<<BUILD_GRID, T>>>(senders, receivers, edges, nodes, W1, W2);
    k_scan<<<SNB, SCB>>>();            // one-pass scan + dis + packed (off,dis)
    k_fill<<<(NE + T - 1) / T, T>>>(senders, receivers, edges);

    const int AGG_GRID  = (NN * 32 + T - 1) / T;       // one warp per node
    const int GEMM_GRID = (NN + 127) / 128;            // 782 tiles

    // layer 1: gather g_xh -> g_xh2 (fp16)
    k_agg<<<AGG_GRID, T>>>(1);
    k_gemm_mma<<<GEMM_GRID, T, SMEM_GEMM>>>(b1, nullptr, 1);
    // layer 2: gather g_xh2 -> out (fp32)
    k_agg<<<AGG_GRID, T>>>(2);
    k_gemm_mma<<<GEMM_GRID, T, SMEM_GEMM>>>(b2, out, 2);
}